// round 2
// baseline (speedup 1.0000x reference)
#include <cuda_runtime.h>
#include <cuda_bf16.h>
#include <cstdint>
#include <math.h>

#define B_    16
#define N_    8192
#define C_    256
#define HID_  128
#define KEEP_ 5734
#define M_    (B_*N_)   // 131072 rows
#define BANDCAP 4096
#define RPB   16        // refine CTAs per batch

// ---------------- scratch (device globals; no allocation allowed) ----------
__device__ float g_scores[M_];
__device__ int   g_idx[B_*KEEP_];
__device__ float g_T[B_];
__device__ float g_delta[B_];
__device__ int   g_band[B_*BANDCAP];
__device__ int   g_bandcnt[B_];
// W1 fragments pre-packed in mma.m16n8k16 B-operand layout:
// [hl(2)][kt(16)][nt(16)][lane(32)][reg(2)] uint32 (each = 2 bf16)
__device__ __align__(16) uint32_t g_w1frag[2*16*16*32*2];

// ---------------- helpers ---------------------------------------------------
__device__ __forceinline__ uint32_t pack2(__nv_bfloat16 lo, __nv_bfloat16 hi) {
    uint16_t a = __bfloat16_as_ushort(lo);
    uint16_t b = __bfloat16_as_ushort(hi);
    return ((uint32_t)b << 16) | (uint32_t)a;
}

__device__ __forceinline__ void mma16816(float* c, const uint32_t* a,
                                         uint32_t b0, uint32_t b1) {
    asm volatile(
        "mma.sync.aligned.m16n8k16.row.col.f32.bf16.bf16.f32 "
        "{%0,%1,%2,%3},{%4,%5,%6,%7},{%8,%9},{%0,%1,%2,%3};\n"
        : "+f"(c[0]), "+f"(c[1]), "+f"(c[2]), "+f"(c[3])
        : "r"(a[0]), "r"(a[1]), "r"(a[2]), "r"(a[3]), "r"(b0), "r"(b1));
}

__device__ __forceinline__ float gelu_exact(float x) {
    return 0.5f * x * (1.0f + erff(x * 0.70710678118654752f));
}

__device__ __forceinline__ uint32_t fmap(float f) {
    uint32_t v = __float_as_uint(f);
    return (v & 0x80000000u) ? ~v : (v | 0x80000000u);
}
__device__ __forceinline__ float funmap(uint32_t k) {
    return (k & 0x80000000u) ? __uint_as_float(k ^ 0x80000000u)
                             : __uint_as_float(~k);
}

// ---------------- kernel 1: pack W1 into hi/lo bf16 mma fragments ----------
__global__ void prep_w1(const float* __restrict__ W1) {
    int id = blockIdx.x * blockDim.x + threadIdx.x;
    if (id >= 2*16*16*32*2) return;
    int r    = id & 1;
    int lane = (id >> 1) & 31;
    int nt   = (id >> 6) & 15;
    int kt   = (id >> 10) & 15;
    int hl   = (id >> 14) & 1;
    int t = lane & 3, g = lane >> 2;
    int k0 = kt*16 + t*2 + r*8;
    int n  = nt*8 + g;
    float w0 = W1[k0*HID_ + n];
    float w1 = W1[(k0+1)*HID_ + n];
    __nv_bfloat16 h0 = __float2bfloat16(w0);
    __nv_bfloat16 h1 = __float2bfloat16(w1);
    __nv_bfloat16 v0, v1;
    if (hl == 0) { v0 = h0; v1 = h1; }
    else {
        v0 = __float2bfloat16(w0 - __bfloat162float(h0));
        v1 = __float2bfloat16(w1 - __bfloat162float(h1));
    }
    g_w1frag[id] = pack2(v0, v1);
}

// ---------------- kernel 2: fused fc1 -> GELU -> fc2 -> approx scores ------
#define ASTRIDE 264   // 256 + 8 bf16 pad -> conflict-free frag reads

__global__ void __launch_bounds__(64)
gemm_scores(const float* __restrict__ tokens,
            const float* __restrict__ b1,
            const float* __restrict__ W2) {
    extern __shared__ __nv_bfloat16 smem[];
    __nv_bfloat16* sHi = smem;                  // [64][ASTRIDE]
    __nv_bfloat16* sLo = smem + 64*ASTRIDE;
    __shared__ float s_b1[HID_], s_w2[HID_];

    const int tid = threadIdx.x;
    for (int i = tid; i < HID_; i += 64) { s_b1[i] = b1[i]; s_w2[i] = W2[i]; }

    const int row0 = blockIdx.x * 64;

    const float4* src = (const float4*)(tokens + (long long)row0 * C_);
    for (int i = tid; i < 64*64; i += 64) {
        int r = i >> 6, c4 = i & 63;
        float4 v = src[i];
        int base = r*ASTRIDE + c4*4;
        float xs[4] = {v.x, v.y, v.z, v.w};
        #pragma unroll
        for (int j = 0; j < 4; j++) {
            __nv_bfloat16 h = __float2bfloat16(xs[j]);
            sHi[base + j] = h;
            sLo[base + j] = __float2bfloat16(xs[j] - __bfloat162float(h));
        }
    }
    __syncthreads();

    const int warp = tid >> 5, lane = tid & 31;
    const int g = lane >> 2, t = lane & 3;
    const int rbase = warp * 32;

    float acc[2][16][4];
    #pragma unroll
    for (int m = 0; m < 2; m++)
        #pragma unroll
        for (int n = 0; n < 16; n++)
            #pragma unroll
            for (int q = 0; q < 4; q++) acc[m][n][q] = 0.0f;

    const uint2* bpH = (const uint2*)g_w1frag;                 // hi frags
    const uint2* bpL = (const uint2*)g_w1frag + 16*16*32;      // lo frags

    for (int kt = 0; kt < 16; kt++) {
        uint32_t a[2][2][4];   // [mtile][hi/lo][reg]
        int col = kt*16 + t*2;
        #pragma unroll
        for (int mt = 0; mt < 2; mt++) {
            int r0 = rbase + mt*16 + g;
            a[mt][0][0] = *(const uint32_t*)&sHi[r0*ASTRIDE + col];
            a[mt][0][1] = *(const uint32_t*)&sHi[(r0+8)*ASTRIDE + col];
            a[mt][0][2] = *(const uint32_t*)&sHi[r0*ASTRIDE + col + 8];
            a[mt][0][3] = *(const uint32_t*)&sHi[(r0+8)*ASTRIDE + col + 8];
            a[mt][1][0] = *(const uint32_t*)&sLo[r0*ASTRIDE + col];
            a[mt][1][1] = *(const uint32_t*)&sLo[(r0+8)*ASTRIDE + col];
            a[mt][1][2] = *(const uint32_t*)&sLo[r0*ASTRIDE + col + 8];
            a[mt][1][3] = *(const uint32_t*)&sLo[(r0+8)*ASTRIDE + col + 8];
        }
        const uint2* bH = bpH + kt*16*32 + lane;
        const uint2* bL = bpL + kt*16*32 + lane;
        #pragma unroll
        for (int nt = 0; nt < 16; nt++) {
            uint2 bh = bH[nt*32];
            uint2 bl = bL[nt*32];
            #pragma unroll
            for (int mt = 0; mt < 2; mt++) {
                mma16816(acc[mt][nt], a[mt][0], bh.x, bh.y);
                mma16816(acc[mt][nt], a[mt][0], bl.x, bl.y);
                mma16816(acc[mt][nt], a[mt][1], bh.x, bh.y);
            }
        }
    }

    #pragma unroll
    for (int mt = 0; mt < 2; mt++) {
        float p0 = 0.0f, p1 = 0.0f;
        #pragma unroll
        for (int nt = 0; nt < 16; nt++) {
            int c0 = nt*8 + t*2, c1 = c0 + 1;
            p0 += gelu_exact(acc[mt][nt][0] + s_b1[c0]) * s_w2[c0];
            p0 += gelu_exact(acc[mt][nt][1] + s_b1[c1]) * s_w2[c1];
            p1 += gelu_exact(acc[mt][nt][2] + s_b1[c0]) * s_w2[c0];
            p1 += gelu_exact(acc[mt][nt][3] + s_b1[c1]) * s_w2[c1];
        }
        p0 += __shfl_xor_sync(0xffffffffu, p0, 1);
        p0 += __shfl_xor_sync(0xffffffffu, p0, 2);
        p1 += __shfl_xor_sync(0xffffffffu, p1, 1);
        p1 += __shfl_xor_sync(0xffffffffu, p1, 2);
        if (t == 0) {
            int grow = row0 + rbase + mt*16 + g;
            g_scores[grow]     = p0;
            g_scores[grow + 8] = p1;
        }
    }
}

// ---------------- radix select core (device) --------------------------------
// finds the KEEP_-th largest key; returns (threshold key, #equals to keep)
struct SelResult { uint32_t T; int need_eq; };

__device__ SelResult radix_select_smem(const uint32_t* keys, int tid,
                                       int* hist, int* sh_Krem,
                                       uint32_t* sh_prefix) {
    if (tid == 0) { *sh_Krem = KEEP_; *sh_prefix = 0u; }
    __syncthreads();
    for (int level = 0; level < 4; level++) {
        int shift = 24 - 8*level;
        if (tid < 256) hist[tid] = 0;
        __syncthreads();
        uint32_t pmask = (level == 0) ? 0u : (0xFFFFFFFFu << (shift + 8));
        uint32_t pref = *sh_prefix;
        for (int i = tid; i < N_; i += 1024) {
            uint32_t v = keys[i];
            if ((v & pmask) == pref) atomicAdd(&hist[(v >> shift) & 255], 1);
        }
        __syncthreads();
        if (tid == 0) {
            int K = *sh_Krem, cum = 0;
            for (int d = 255; d >= 0; d--) {
                int c = hist[d];
                if (cum + c >= K) {
                    *sh_prefix = pref | ((uint32_t)d << shift);
                    *sh_Krem = K - cum;
                    break;
                }
                cum += c;
            }
        }
        __syncthreads();
    }
    SelResult r; r.T = *sh_prefix; r.need_eq = *sh_Krem;
    __syncthreads();
    return r;
}

// ---------------- kernel 3: approx threshold + band collection -------------
__global__ void __launch_bounds__(1024) band_setup() {
    __shared__ uint32_t keys[N_];     // 32 KB
    __shared__ int hist[256];
    __shared__ int sh_Krem;
    __shared__ uint32_t sh_prefix;
    __shared__ float s_ss;

    const int b = blockIdx.x, tid = threadIdx.x;
    const int lane = tid & 31;

    if (tid == 0) { s_ss = 0.0f; g_bandcnt[b] = 0; }
    __syncthreads();

    float lss = 0.0f;
    for (int i = tid; i < N_; i += 1024) {
        float s = g_scores[b*N_ + i];
        lss += s * s;
        keys[i] = fmap(s);
    }
    #pragma unroll
    for (int o = 16; o; o >>= 1) lss += __shfl_xor_sync(0xffffffffu, lss, o);
    if (lane == 0) atomicAdd(&s_ss, lss);
    __syncthreads();

    SelResult sel = radix_select_smem(keys, tid, hist, &sh_Krem, &sh_prefix);
    float Tf = funmap(sel.T);
    float delta = 0.02f * sqrtf(s_ss / (float)N_) + 1e-6f;
    if (tid == 0) { g_T[b] = Tf; g_delta[b] = delta; }

    for (int i = tid; i < N_; i += 1024) {
        float s = g_scores[b*N_ + i];
        if (fabsf(s - Tf) <= delta) {
            int p = atomicAdd(&g_bandcnt[b], 1);
            if (p < BANDCAP) g_band[b*BANDCAP + p] = i;
        }
    }
}

// ---------------- kernel 4: exact fp64 rescore of band rows ----------------
__global__ void __launch_bounds__(256)
refine_band(const float* __restrict__ tokens, const float* __restrict__ W1,
            const float* __restrict__ b1, const float* __restrict__ W2) {
    extern __shared__ float sx[];   // [8 warps][8 rows][256]
    const int b   = blockIdx.x / RPB;
    const int sub = blockIdx.x % RPB;
    const int warp = threadIdx.x >> 5, lane = threadIdx.x & 31;
    const int cnt = min(g_bandcnt[b], BANDCAP);
    const int wg = sub*8 + warp;           // 0..127 global warp per batch

    float* xw = sx + warp * 8 * 256;

    for (int base = wg*8; base < cnt; base += 128*8) {
        int nrows = min(8, cnt - base);
        for (int j = 0; j < nrows; j++) {
            int r = g_band[b*BANDCAP + base + j];
            const float4* src = (const float4*)(tokens + ((long long)(b*N_ + r)) * C_);
            ((float4*)(xw + j*256))[lane]      = src[lane];
            ((float4*)(xw + j*256))[lane + 32] = src[lane + 32];
        }
        __syncwarp();

        double acc[8][4];
        #pragma unroll
        for (int j = 0; j < 8; j++)
            #pragma unroll
            for (int q = 0; q < 4; q++) acc[j][q] = 0.0;

        for (int k = 0; k < C_; k++) {
            float4 w = ((const float4*)(W1 + k*HID_))[lane];
            double w0 = (double)w.x, w1 = (double)w.y;
            double w2d = (double)w.z, w3 = (double)w.w;
            #pragma unroll
            for (int j = 0; j < 8; j++) {
                double xd = (double)xw[j*256 + k];
                acc[j][0] += xd * w0;
                acc[j][1] += xd * w1;
                acc[j][2] += xd * w2d;
                acc[j][3] += xd * w3;
            }
        }

        for (int j = 0; j < nrows; j++) {
            double s = 0.0;
            #pragma unroll
            for (int q = 0; q < 4; q++) {
                int h = lane*4 + q;
                double hv = acc[j][q] + (double)b1[h];
                double gl = 0.5 * hv * (1.0 + erf(hv * 0.70710678118654752440));
                s += gl * (double)W2[h];
            }
            #pragma unroll
            for (int o = 16; o; o >>= 1) s += __shfl_xor_sync(0xffffffffu, s, o);
            if (lane == 0) {
                int r = g_band[b*BANDCAP + base + j];
                g_scores[b*N_ + r] = (float)s;
            }
        }
        __syncwarp();
    }
}

// ---------------- kernel 5: exact top-K per batch on refined scores --------
__device__ __forceinline__ int block_exscan(int v, int* sw, int tid) {
    int lane = tid & 31, w = tid >> 5;
    int x = v;
    #pragma unroll
    for (int o = 1; o < 32; o <<= 1) {
        int y = __shfl_up_sync(0xffffffffu, x, o);
        if (lane >= o) x += y;
    }
    __syncthreads();
    if (lane == 31) sw[w] = x;
    __syncthreads();
    if (w == 0) {
        int s = sw[lane];
        #pragma unroll
        for (int o = 1; o < 32; o <<= 1) {
            int y = __shfl_up_sync(0xffffffffu, s, o);
            if (lane >= o) s += y;
        }
        sw[lane] = s;
    }
    __syncthreads();
    int base = (w == 0) ? 0 : sw[w-1];
    return base + x - v;
}

__global__ void __launch_bounds__(1024) select_topk() {
    __shared__ uint32_t keys[N_];     // 32 KB
    __shared__ int hist[256];
    __shared__ int sw[32];
    __shared__ int sh_Krem;
    __shared__ uint32_t sh_prefix;

    const int b = blockIdx.x, tid = threadIdx.x;

    for (int i = tid; i < N_; i += 1024)
        keys[i] = fmap(g_scores[b*N_ + i]);
    __syncthreads();

    SelResult sel = radix_select_smem(keys, tid, hist, &sh_Krem, &sh_prefix);
    const uint32_t T = sel.T;
    const int need_eq = sel.need_eq;

    const int base_i = tid * 8;
    int eqc = 0;
    #pragma unroll
    for (int j = 0; j < 8; j++) eqc += (keys[base_i + j] == T);
    int e = block_exscan(eqc, sw, tid);

    int keepc = 0;
    unsigned char kp[8];
    #pragma unroll
    for (int j = 0; j < 8; j++) {
        uint32_t v = keys[base_i + j];
        bool k = (v > T);
        if (v == T) { k = (e < need_eq); e++; }
        kp[j] = k; keepc += k;
    }
    int pos = block_exscan(keepc, sw, tid);
    #pragma unroll
    for (int j = 0; j < 8; j++) {
        if (kp[j]) { g_idx[b*KEEP_ + pos] = base_i + j; pos++; }
    }
}

// ---------------- kernel 6: gather pruned tokens + emit indices ------------
__global__ void __launch_bounds__(256)
gather_rows(const float* __restrict__ tokens, float* __restrict__ out,
            int write_idx) {
    int rid = blockIdx.x * 8 + (threadIdx.x >> 5);
    if (rid >= B_*KEEP_) return;
    int lane = threadIdx.x & 31;
    int b = rid / KEEP_;
    int idx = g_idx[rid];
    const float4* s = (const float4*)(tokens + ((long long)(b*N_ + idx)) * C_);
    float4* d = (float4*)(out + (long long)rid * C_);
    d[lane]      = s[lane];
    d[lane + 32] = s[lane + 32];
    if (write_idx && lane == 0)
        out[(long long)B_*KEEP_*C_ + rid] = (float)idx;
}

// ---------------- launch ----------------------------------------------------
extern "C" void kernel_launch(void* const* d_in, const int* in_sizes, int n_in,
                              void* d_out, int out_size) {
    const float* tokens = (const float*)d_in[0];
    const float* W1     = (const float*)d_in[1];
    const float* b1     = (const float*)d_in[2];
    const float* W2     = (const float*)d_in[3];
    // b2 shifts all scores equally -> selection-invariant; not in output.

    prep_w1<<<32, 1024>>>(W1);

    const int smem_bytes = 2 * 64 * ASTRIDE * (int)sizeof(__nv_bfloat16); // 67584
    cudaFuncSetAttribute(gemm_scores,
                         cudaFuncAttributeMaxDynamicSharedMemorySize, smem_bytes);
    gemm_scores<<<M_/64, 64, smem_bytes>>>(tokens, b1, W2);

    band_setup<<<B_, 1024>>>();

    const int refine_smem = 8 * 8 * 256 * (int)sizeof(float);  // 65536
    cudaFuncSetAttribute(refine_band,
                         cudaFuncAttributeMaxDynamicSharedMemorySize, refine_smem);
    refine_band<<<B_*RPB, 256, refine_smem>>>(tokens, W1, b1, W2);

    select_topk<<<B_, 1024>>>();

    long long prunedN = (long long)B_ * KEEP_ * C_;
    int wi = ((long long)out_size >= prunedN + (long long)B_*KEEP_) ? 1 : 0;
    gather_rows<<<(B_*KEEP_ + 7)/8, 256>>>(tokens, (float*)d_out, wi);
}

// round 3
// speedup vs baseline: 3.1278x; 3.1278x over previous
#include <cuda_runtime.h>
#include <cuda_bf16.h>
#include <cstdint>
#include <math.h>

#define B_    16
#define N_    8192
#define C_    256
#define HID_  128
#define KEEP_ 5734
#define M_    (B_*N_)   // 131072 rows
#define BANDCAP 4096

// ---------------- scratch (device globals; no allocation allowed) ----------
__device__ float g_scores[M_];
__device__ int   g_idx[B_*KEEP_];
__device__ int   g_band[B_*BANDCAP];
__device__ int   g_bandcnt[B_];
// W1 fragments, mma.m16n8k16 B-operand layout, hi+lo fused:
// [kt(16)][nt(16)][lane(32)] uint4 = (hi.b0, hi.b1, lo.b0, lo.b1)
__device__ __align__(16) uint4 g_w1frag[16*16*32];

// ---------------- helpers ---------------------------------------------------
__device__ __forceinline__ uint32_t pack2(__nv_bfloat16 lo, __nv_bfloat16 hi) {
    uint16_t a = __bfloat16_as_ushort(lo);
    uint16_t b = __bfloat16_as_ushort(hi);
    return ((uint32_t)b << 16) | (uint32_t)a;
}

__device__ __forceinline__ void mma16816(float* c, const uint32_t* a,
                                         uint32_t b0, uint32_t b1) {
    asm volatile(
        "mma.sync.aligned.m16n8k16.row.col.f32.bf16.bf16.f32 "
        "{%0,%1,%2,%3},{%4,%5,%6,%7},{%8,%9},{%0,%1,%2,%3};\n"
        : "+f"(c[0]), "+f"(c[1]), "+f"(c[2]), "+f"(c[3])
        : "r"(a[0]), "r"(a[1]), "r"(a[2]), "r"(a[3]), "r"(b0), "r"(b1));
}

__device__ __forceinline__ float gelu_exact(float x) {
    return 0.5f * x * (1.0f + erff(x * 0.70710678118654752f));
}

__device__ __forceinline__ uint32_t fmap(float f) {
    uint32_t v = __float_as_uint(f);
    return (v & 0x80000000u) ? ~v : (v | 0x80000000u);
}
__device__ __forceinline__ float funmap(uint32_t k) {
    return (k & 0x80000000u) ? __uint_as_float(k ^ 0x80000000u)
                             : __uint_as_float(~k);
}

// split a float2 into bf16 hi pair (returned) and lo pair (out param)
__device__ __forceinline__ uint32_t split2(float2 f, uint32_t& lo) {
    __nv_bfloat16 hx = __float2bfloat16(f.x);
    __nv_bfloat16 hy = __float2bfloat16(f.y);
    lo = pack2(__float2bfloat16(f.x - __bfloat162float(hx)),
               __float2bfloat16(f.y - __bfloat162float(hy)));
    return pack2(hx, hy);
}

// ---------------- kernel 1: pack W1 into fused hi/lo mma fragments ---------
__global__ void prep_w1(const float* __restrict__ W1) {
    int id = blockIdx.x * blockDim.x + threadIdx.x;   // 8192 total
    if (id >= 16*16*32) return;
    int lane = id & 31;
    int kt   = id >> 9;          // (id >> 5) / 16
    int t = lane & 3, g = lane >> 2;
    // n col comes from nt = (id>>5)&15
    int nt = (id >> 5) & 15;
    int n  = nt*8 + g;
    int k0 = kt*16 + t*2;
    float w00 = W1[k0*HID_ + n],     w01 = W1[(k0+1)*HID_ + n];
    float w10 = W1[(k0+8)*HID_ + n], w11 = W1[(k0+9)*HID_ + n];
    __nv_bfloat16 h00 = __float2bfloat16(w00), h01 = __float2bfloat16(w01);
    __nv_bfloat16 h10 = __float2bfloat16(w10), h11 = __float2bfloat16(w11);
    uint4 v;
    v.x = pack2(h00, h01);
    v.y = pack2(h10, h11);
    v.z = pack2(__float2bfloat16(w00 - __bfloat162float(h00)),
                __float2bfloat16(w01 - __bfloat162float(h01)));
    v.w = pack2(__float2bfloat16(w10 - __bfloat162float(h10)),
                __float2bfloat16(w11 - __bfloat162float(h11)));
    g_w1frag[id] = v;
}

// ---------------- kernel 2: fused fc1 -> GELU -> fc2 -> approx scores ------
// 256 threads = 8 warps; each warp computes a 16-row x 128-col tile.
// A fragments loaded directly from global (fp32 pairs), split hi/lo inline.
// acc = Ahi*Whi + Ahi*Wlo + Alo*Whi  (fp32 accumulate, err ~1e-5 rel)
__global__ void __launch_bounds__(256, 2)
gemm_scores(const float* __restrict__ tokens,
            const float* __restrict__ b1,
            const float* __restrict__ W2) {
    __shared__ float s_b1[HID_], s_w2[HID_];
    const int tid = threadIdx.x;
    if (tid < HID_) { s_b1[tid] = b1[tid]; s_w2[tid] = W2[tid]; }
    __syncthreads();

    const int warp = tid >> 5, lane = tid & 31;
    const int g = lane >> 2, t = lane & 3;
    const long long row0 = (long long)(blockIdx.x * 8 + warp) * 16;
    const float* A0 = tokens + row0 * C_;

    float acc[16][4];
    #pragma unroll
    for (int n = 0; n < 16; n++)
        #pragma unroll
        for (int q = 0; q < 4; q++) acc[n][q] = 0.0f;

    const uint4* Bf = g_w1frag + lane;

    #pragma unroll 4
    for (int kt = 0; kt < 16; kt++) {
        const int col = kt*16 + t*2;
        float2 f0 = *(const float2*)(A0 + (g)     * C_ + col);
        float2 f1 = *(const float2*)(A0 + (g + 8) * C_ + col);
        float2 f2 = *(const float2*)(A0 + (g)     * C_ + col + 8);
        float2 f3 = *(const float2*)(A0 + (g + 8) * C_ + col + 8);
        uint32_t aH[4], aL[4];
        aH[0] = split2(f0, aL[0]);
        aH[1] = split2(f1, aL[1]);
        aH[2] = split2(f2, aL[2]);
        aH[3] = split2(f3, aL[3]);

        const uint4* bp = Bf + kt*16*32;
        #pragma unroll
        for (int nt = 0; nt < 16; nt++) {
            uint4 bb = bp[nt*32];
            mma16816(acc[nt], aH, bb.x, bb.y);
            mma16816(acc[nt], aH, bb.z, bb.w);
            mma16816(acc[nt], aL, bb.x, bb.y);
        }
    }

    // epilogue: GELU + dot with W2, reduce over the 4-lane quad (t)
    float p0 = 0.0f, p1 = 0.0f;
    #pragma unroll
    for (int nt = 0; nt < 16; nt++) {
        int c0 = nt*8 + t*2, c1 = c0 + 1;
        p0 += gelu_exact(acc[nt][0] + s_b1[c0]) * s_w2[c0];
        p0 += gelu_exact(acc[nt][1] + s_b1[c1]) * s_w2[c1];
        p1 += gelu_exact(acc[nt][2] + s_b1[c0]) * s_w2[c0];
        p1 += gelu_exact(acc[nt][3] + s_b1[c1]) * s_w2[c1];
    }
    p0 += __shfl_xor_sync(0xffffffffu, p0, 1);
    p0 += __shfl_xor_sync(0xffffffffu, p0, 2);
    p1 += __shfl_xor_sync(0xffffffffu, p1, 1);
    p1 += __shfl_xor_sync(0xffffffffu, p1, 2);
    if (t == 0) {
        g_scores[row0 + g]     = p0;
        g_scores[row0 + 8 + g] = p1;
    }
}

// ---------------- radix select core (device) --------------------------------
struct SelResult { uint32_t T; int need_eq; };

__device__ SelResult radix_select_smem(const uint32_t* keys, int tid,
                                       int* hist, int* sh_Krem,
                                       uint32_t* sh_prefix) {
    if (tid == 0) { *sh_Krem = KEEP_; *sh_prefix = 0u; }
    __syncthreads();
    for (int level = 0; level < 4; level++) {
        int shift = 24 - 8*level;
        if (tid < 256) hist[tid] = 0;
        __syncthreads();
        uint32_t pmask = (level == 0) ? 0u : (0xFFFFFFFFu << (shift + 8));
        uint32_t pref = *sh_prefix;
        for (int i = tid; i < N_; i += 1024) {
            uint32_t v = keys[i];
            if ((v & pmask) == pref) atomicAdd(&hist[(v >> shift) & 255], 1);
        }
        __syncthreads();
        if (tid == 0) {
            int K = *sh_Krem, cum = 0;
            for (int d = 255; d >= 0; d--) {
                int c = hist[d];
                if (cum + c >= K) {
                    *sh_prefix = pref | ((uint32_t)d << shift);
                    *sh_Krem = K - cum;
                    break;
                }
                cum += c;
            }
        }
        __syncthreads();
    }
    SelResult r; r.T = *sh_prefix; r.need_eq = *sh_Krem;
    __syncthreads();
    return r;
}

// ---------------- kernel 3: approx threshold + band collection -------------
__global__ void __launch_bounds__(1024) band_setup() {
    __shared__ uint32_t keys[N_];
    __shared__ int hist[256];
    __shared__ int sh_Krem;
    __shared__ uint32_t sh_prefix;
    __shared__ float s_ss;

    const int b = blockIdx.x, tid = threadIdx.x;
    const int lane = tid & 31;

    if (tid == 0) { s_ss = 0.0f; g_bandcnt[b] = 0; }
    __syncthreads();

    float lss = 0.0f;
    for (int i = tid; i < N_; i += 1024) {
        float s = g_scores[b*N_ + i];
        lss += s * s;
        keys[i] = fmap(s);
    }
    #pragma unroll
    for (int o = 16; o; o >>= 1) lss += __shfl_xor_sync(0xffffffffu, lss, o);
    if (lane == 0) atomicAdd(&s_ss, lss);
    __syncthreads();

    SelResult sel = radix_select_smem(keys, tid, hist, &sh_Krem, &sh_prefix);
    float Tf = funmap(sel.T);
    float delta = 0.02f * sqrtf(s_ss / (float)N_) + 1e-6f;

    for (int i = tid; i < N_; i += 1024) {
        float s = g_scores[b*N_ + i];
        if (fabsf(s - Tf) <= delta) {
            int p = atomicAdd(&g_bandcnt[b], 1);
            if (p < BANDCAP) g_band[b*BANDCAP + p] = i;
        }
    }
}

// ---------------- kernel 4: near-exact rescore of band rows ----------------
// fp32 Dot2 (TwoProdFMA + 2Sum) accumulation == fp64-grade accuracy at FFMA
// rates; double only for the GELU epilogue (128 erf per row).
__global__ void __launch_bounds__(256)
refine_band(const float* __restrict__ tokens, const float* __restrict__ W1,
            const float* __restrict__ b1, const float* __restrict__ W2) {
    __shared__ float sx[8][4*256 + 4];   // 4 rows per warp
    const int b   = blockIdx.x >> 1;
    const int sub = blockIdx.x & 1;
    const int warp = threadIdx.x >> 5, lane = threadIdx.x & 31;
    const int cnt = min(g_bandcnt[b], BANDCAP);
    const int wg = sub*8 + warp;                 // 0..15 warp per batch

    float* xw = sx[warp];

    for (int base = wg*4; base < cnt; base += 16*4) {
        const int nrows = min(4, cnt - base);
        for (int j = 0; j < nrows; j++) {
            int r = g_band[b*BANDCAP + base + j];
            const float4* src = (const float4*)(tokens + ((long long)(b*N_ + r)) * C_);
            ((float4*)(xw + j*256))[lane]      = src[lane];
            ((float4*)(xw + j*256))[lane + 32] = src[lane + 32];
        }
        __syncwarp();

        float s[4][4], cc[4][4];
        #pragma unroll
        for (int j = 0; j < 4; j++)
            #pragma unroll
            for (int q = 0; q < 4; q++) { s[j][q] = 0.0f; cc[j][q] = 0.0f; }

        for (int k = 0; k < C_; k++) {
            float4 w = __ldg((const float4*)(W1 + k*HID_) + lane);
            float wq[4] = {w.x, w.y, w.z, w.w};
            #pragma unroll
            for (int j = 0; j < 4; j++) {
                float xk = xw[j*256 + k];
                #pragma unroll
                for (int q = 0; q < 4; q++) {
                    float p  = xk * wq[q];
                    float e  = fmaf(xk, wq[q], -p);      // exact product err
                    float tn = s[j][q] + p;              // 2Sum
                    float z  = tn - s[j][q];
                    float e2 = (s[j][q] - (tn - z)) + (p - z);
                    s[j][q] = tn;
                    cc[j][q] += e + e2;
                }
            }
        }

        for (int j = 0; j < nrows; j++) {
            double sd = 0.0;
            #pragma unroll
            for (int q = 0; q < 4; q++) {
                int h = lane*4 + q;
                double hv = (double)s[j][q] + (double)cc[j][q] + (double)b1[h];
                double gl = 0.5 * hv * (1.0 + erf(hv * 0.70710678118654752440));
                sd += gl * (double)W2[h];
            }
            #pragma unroll
            for (int o = 16; o; o >>= 1)
                sd += __shfl_xor_sync(0xffffffffu, sd, o);
            if (lane == 0) {
                int r = g_band[b*BANDCAP + base + j];
                g_scores[b*N_ + r] = (float)sd;
            }
        }
        __syncwarp();
    }
}

// ---------------- kernel 5: exact top-K per batch on refined scores --------
__device__ __forceinline__ int block_exscan(int v, int* sw, int tid) {
    int lane = tid & 31, w = tid >> 5;
    int x = v;
    #pragma unroll
    for (int o = 1; o < 32; o <<= 1) {
        int y = __shfl_up_sync(0xffffffffu, x, o);
        if (lane >= o) x += y;
    }
    __syncthreads();
    if (lane == 31) sw[w] = x;
    __syncthreads();
    if (w == 0) {
        int s = sw[lane];
        #pragma unroll
        for (int o = 1; o < 32; o <<= 1) {
            int y = __shfl_up_sync(0xffffffffu, s, o);
            if (lane >= o) s += y;
        }
        sw[lane] = s;
    }
    __syncthreads();
    int base = (w == 0) ? 0 : sw[w-1];
    return base + x - v;
}

__global__ void __launch_bounds__(1024) select_topk() {
    __shared__ uint32_t keys[N_];
    __shared__ int hist[256];
    __shared__ int sw[32];
    __shared__ int sh_Krem;
    __shared__ uint32_t sh_prefix;

    const int b = blockIdx.x, tid = threadIdx.x;

    for (int i = tid; i < N_; i += 1024)
        keys[i] = fmap(g_scores[b*N_ + i]);
    __syncthreads();

    SelResult sel = radix_select_smem(keys, tid, hist, &sh_Krem, &sh_prefix);
    const uint32_t T = sel.T;
    const int need_eq = sel.need_eq;

    const int base_i = tid * 8;
    int eqc = 0;
    #pragma unroll
    for (int j = 0; j < 8; j++) eqc += (keys[base_i + j] == T);
    int e = block_exscan(eqc, sw, tid);

    int keepc = 0;
    unsigned char kp[8];
    #pragma unroll
    for (int j = 0; j < 8; j++) {
        uint32_t v = keys[base_i + j];
        bool k = (v > T);
        if (v == T) { k = (e < need_eq); e++; }
        kp[j] = k; keepc += k;
    }
    int pos = block_exscan(keepc, sw, tid);
    #pragma unroll
    for (int j = 0; j < 8; j++) {
        if (kp[j]) { g_idx[b*KEEP_ + pos] = base_i + j; pos++; }
    }
}

// ---------------- kernel 6: gather pruned tokens + emit indices ------------
__global__ void __launch_bounds__(512)
gather_rows(const float* __restrict__ tokens, float* __restrict__ out,
            int write_idx) {
    int rid = blockIdx.x * 16 + (threadIdx.x >> 5);
    if (rid >= B_*KEEP_) return;
    int lane = threadIdx.x & 31;
    int b = rid / KEEP_;
    int idx = g_idx[rid];
    const float4* s = (const float4*)(tokens + ((long long)(b*N_ + idx)) * C_);
    float4* d = (float4*)(out + (long long)rid * C_);
    d[lane]      = s[lane];
    d[lane + 32] = s[lane + 32];
    if (write_idx && lane == 0)
        out[(long long)B_*KEEP_*C_ + rid] = (float)idx;
}

// ---------------- launch ----------------------------------------------------
extern "C" void kernel_launch(void* const* d_in, const int* in_sizes, int n_in,
                              void* d_out, int out_size) {
    const float* tokens = (const float*)d_in[0];
    const float* W1     = (const float*)d_in[1];
    const float* b1     = (const float*)d_in[2];
    const float* W2     = (const float*)d_in[3];
    // b2 shifts all scores equally -> selection-invariant; not in output.

    prep_w1<<<32, 256>>>(W1);

    gemm_scores<<<M_/128, 256>>>(tokens, b1, W2);

    band_setup<<<B_, 1024>>>();

    refine_band<<<B_*2, 256>>>(tokens, W1, b1, W2);

    select_topk<<<B_, 1024>>>();

    long long prunedN = (long long)B_ * KEEP_ * C_;
    int wi = ((long long)out_size >= prunedN + (long long)B_*KEEP_) ? 1 : 0;
    gather_rows<<<(B_*KEEP_ + 15)/16, 512>>>(tokens, (float*)d_out, wi);
}

// round 4
// speedup vs baseline: 6.9867x; 2.2338x over previous
#include <cuda_runtime.h>
#include <cuda_bf16.h>
#include <cstdint>
#include <math.h>

#define B_    16
#define N_    8192
#define C_    256
#define HID_  128
#define KEEP_ 5734
#define M_    (B_*N_)   // 131072 rows
#define BANDCAP 4096

// ---------------- scratch (device globals; no allocation allowed) ----------
__device__ float g_scores[M_];
__device__ int   g_idx[B_*KEEP_];
__device__ int   g_band[B_*BANDCAP];
__device__ int   g_bandcnt[B_];
// W1 fragments, mma.m16n8k16 B-operand layout (bf16 RN):
// [kt(16)][nt(16)][lane(32)] uint2 = (b0, b1)
__device__ __align__(16) uint2 g_w1frag[16*16*32];

// ---------------- helpers ---------------------------------------------------
__device__ __forceinline__ uint32_t pack2(__nv_bfloat16 lo, __nv_bfloat16 hi) {
    uint16_t a = __bfloat16_as_ushort(lo);
    uint16_t b = __bfloat16_as_ushort(hi);
    return ((uint32_t)b << 16) | (uint32_t)a;
}

__device__ __forceinline__ uint32_t cvt2(float2 f) {
    __nv_bfloat162 h = __float22bfloat162_rn(f);
    return *(uint32_t*)&h;
}

__device__ __forceinline__ void mma16816(float* c, const uint32_t* a,
                                         uint32_t b0, uint32_t b1) {
    asm volatile(
        "mma.sync.aligned.m16n8k16.row.col.f32.bf16.bf16.f32 "
        "{%0,%1,%2,%3},{%4,%5,%6,%7},{%8,%9},{%0,%1,%2,%3};\n"
        : "+f"(c[0]), "+f"(c[1]), "+f"(c[2]), "+f"(c[3])
        : "r"(a[0]), "r"(a[1]), "r"(a[2]), "r"(a[3]), "r"(b0), "r"(b1));
}

__device__ __forceinline__ float gelu_exact(float x) {
    return 0.5f * x * (1.0f + erff(x * 0.70710678118654752f));
}

__device__ __forceinline__ uint32_t fmap(float f) {
    uint32_t v = __float_as_uint(f);
    return (v & 0x80000000u) ? ~v : (v | 0x80000000u);
}
__device__ __forceinline__ float funmap(uint32_t k) {
    return (k & 0x80000000u) ? __uint_as_float(k ^ 0x80000000u)
                             : __uint_as_float(~k);
}

// ---------------- kernel 1: pack W1 into bf16 mma fragments ----------------
__global__ void prep_w1(const float* __restrict__ W1) {
    int id = blockIdx.x * blockDim.x + threadIdx.x;   // 8192 total
    if (id >= 16*16*32) return;
    int lane = id & 31;
    int kt   = id >> 9;
    int t = lane & 3, g = lane >> 2;
    int nt = (id >> 5) & 15;
    int n  = nt*8 + g;
    int k0 = kt*16 + t*2;
    float w00 = W1[k0*HID_ + n],     w01 = W1[(k0+1)*HID_ + n];
    float w10 = W1[(k0+8)*HID_ + n], w11 = W1[(k0+9)*HID_ + n];
    uint2 v;
    v.x = pack2(__float2bfloat16_rn(w00), __float2bfloat16_rn(w01));
    v.y = pack2(__float2bfloat16_rn(w10), __float2bfloat16_rn(w11));
    g_w1frag[id] = v;
}

// ---------------- kernel 2: screen: fc1(bf16 mma) -> GELU -> fc2 -----------
// 256 threads = 8 warps; each warp computes a 16-row x 128-col tile.
// Single bf16 pass: abs err ~1.3e-3 << band half-width (0.04*RMS ~ 2.4e-2).
__global__ void __launch_bounds__(256, 2)
gemm_scores(const float* __restrict__ tokens,
            const float* __restrict__ b1,
            const float* __restrict__ W2) {
    __shared__ float s_b1[HID_], s_w2[HID_];
    const int tid = threadIdx.x;
    if (tid < HID_) { s_b1[tid] = b1[tid]; s_w2[tid] = W2[tid]; }
    __syncthreads();

    const int warp = tid >> 5, lane = tid & 31;
    const int g = lane >> 2, t = lane & 3;
    const long long row0 = (long long)(blockIdx.x * 8 + warp) * 16;
    const float* A0 = tokens + row0 * C_;

    float acc[16][4];
    #pragma unroll
    for (int n = 0; n < 16; n++)
        #pragma unroll
        for (int q = 0; q < 4; q++) acc[n][q] = 0.0f;

    const uint2* Bf = g_w1frag + lane;

    #pragma unroll 4
    for (int kt = 0; kt < 16; kt++) {
        const int col = kt*16 + t*2;
        uint32_t a[4];
        a[0] = cvt2(*(const float2*)(A0 + (g)     * C_ + col));
        a[1] = cvt2(*(const float2*)(A0 + (g + 8) * C_ + col));
        a[2] = cvt2(*(const float2*)(A0 + (g)     * C_ + col + 8));
        a[3] = cvt2(*(const float2*)(A0 + (g + 8) * C_ + col + 8));

        const uint2* bp = Bf + kt*16*32;
        #pragma unroll
        for (int nt = 0; nt < 16; nt++) {
            uint2 bb = bp[nt*32];
            mma16816(acc[nt], a, bb.x, bb.y);
        }
    }

    // epilogue: GELU + dot with W2, reduce over the 4-lane quad (t)
    float p0 = 0.0f, p1 = 0.0f;
    #pragma unroll
    for (int nt = 0; nt < 16; nt++) {
        int c0 = nt*8 + t*2, c1 = c0 + 1;
        p0 += gelu_exact(acc[nt][0] + s_b1[c0]) * s_w2[c0];
        p0 += gelu_exact(acc[nt][1] + s_b1[c1]) * s_w2[c1];
        p1 += gelu_exact(acc[nt][2] + s_b1[c0]) * s_w2[c0];
        p1 += gelu_exact(acc[nt][3] + s_b1[c1]) * s_w2[c1];
    }
    p0 += __shfl_xor_sync(0xffffffffu, p0, 1);
    p0 += __shfl_xor_sync(0xffffffffu, p0, 2);
    p1 += __shfl_xor_sync(0xffffffffu, p1, 1);
    p1 += __shfl_xor_sync(0xffffffffu, p1, 2);
    if (t == 0) {
        g_scores[row0 + g]     = p0;
        g_scores[row0 + 8 + g] = p1;
    }
}

// ---------------- radix select core (device) --------------------------------
struct SelResult { uint32_t T; int need_eq; };

__device__ SelResult radix_select_smem(const uint32_t* keys, int tid,
                                       int* hist, int* sh_Krem,
                                       uint32_t* sh_prefix) {
    if (tid == 0) { *sh_Krem = KEEP_; *sh_prefix = 0u; }
    __syncthreads();
    for (int level = 0; level < 4; level++) {
        int shift = 24 - 8*level;
        if (tid < 256) hist[tid] = 0;
        __syncthreads();
        uint32_t pmask = (level == 0) ? 0u : (0xFFFFFFFFu << (shift + 8));
        uint32_t pref = *sh_prefix;
        for (int i = tid; i < N_; i += 1024) {
            uint32_t v = keys[i];
            if ((v & pmask) == pref) atomicAdd(&hist[(v >> shift) & 255], 1);
        }
        __syncthreads();
        if (tid == 0) {
            int K = *sh_Krem, cum = 0;
            for (int d = 255; d >= 0; d--) {
                int c = hist[d];
                if (cum + c >= K) {
                    *sh_prefix = pref | ((uint32_t)d << shift);
                    *sh_Krem = K - cum;
                    break;
                }
                cum += c;
            }
        }
        __syncthreads();
    }
    SelResult r; r.T = *sh_prefix; r.need_eq = *sh_Krem;
    __syncthreads();
    return r;
}

// ---------------- kernel 3: approx threshold + band collection -------------
__global__ void __launch_bounds__(1024) band_setup() {
    __shared__ uint32_t keys[N_];
    __shared__ int hist[256];
    __shared__ int sh_Krem;
    __shared__ uint32_t sh_prefix;
    __shared__ float s_ss;

    const int b = blockIdx.x, tid = threadIdx.x;
    const int lane = tid & 31;

    if (tid == 0) { s_ss = 0.0f; g_bandcnt[b] = 0; }
    __syncthreads();

    float lss = 0.0f;
    for (int i = tid; i < N_; i += 1024) {
        float s = g_scores[b*N_ + i];
        lss += s * s;
        keys[i] = fmap(s);
    }
    #pragma unroll
    for (int o = 16; o; o >>= 1) lss += __shfl_xor_sync(0xffffffffu, lss, o);
    if (lane == 0) atomicAdd(&s_ss, lss);
    __syncthreads();

    SelResult sel = radix_select_smem(keys, tid, hist, &sh_Krem, &sh_prefix);
    float Tf = funmap(sel.T);
    // bf16 screen err ~1.3e-3 abs; band half-width 0.04*RMS ~ 2.4e-2 -> >15x
    float delta = 0.04f * sqrtf(s_ss / (float)N_) + 1e-5f;

    for (int i = tid; i < N_; i += 1024) {
        float s = g_scores[b*N_ + i];
        if (fabsf(s - Tf) <= delta) {
            int p = atomicAdd(&g_bandcnt[b], 1);
            if (p < BANDCAP) g_band[b*BANDCAP + p] = i;
        }
    }
}

// ---------------- kernel 4: near-exact rescore of band rows ----------------
// One row per warp, spread over the whole chip. fp32 Dot2 accumulation
// (TwoProdFMA + 2Sum) == fp64-grade dot; double only for the GELU epilogue.
__global__ void __launch_bounds__(256)
refine_band(const float* __restrict__ tokens, const float* __restrict__ W1,
            const float* __restrict__ b1, const float* __restrict__ W2) {
    __shared__ float sx[8][C_];
    const int b    = blockIdx.y;
    const int warp = threadIdx.x >> 5, lane = threadIdx.x & 31;
    const int cnt = min(g_bandcnt[b], BANDCAP);
    const int nwarps = gridDim.x * 8;
    const int w0 = blockIdx.x * 8 + warp;

    for (int e = w0; e < cnt; e += nwarps) {
        const int r = g_band[b*BANDCAP + e];
        const float4* src = (const float4*)(tokens + ((long long)(b*N_ + r)) * C_);
        ((float4*)sx[warp])[lane]      = src[lane];
        ((float4*)sx[warp])[lane + 32] = src[lane + 32];
        __syncwarp();

        float s[4], cc[4];
        #pragma unroll
        for (int q = 0; q < 4; q++) { s[q] = 0.0f; cc[q] = 0.0f; }

        #pragma unroll 4
        for (int k = 0; k < C_; k++) {
            float4 wv = __ldg((const float4*)(W1 + k*HID_) + lane);
            float wq[4] = {wv.x, wv.y, wv.z, wv.w};
            float xk = sx[warp][k];
            #pragma unroll
            for (int q = 0; q < 4; q++) {
                float p  = xk * wq[q];
                float er = fmaf(xk, wq[q], -p);      // exact product error
                float tn = s[q] + p;                 // 2Sum
                float z  = tn - s[q];
                float e2 = (s[q] - (tn - z)) + (p - z);
                s[q] = tn;
                cc[q] += er + e2;
            }
        }

        double sd = 0.0;
        #pragma unroll
        for (int q = 0; q < 4; q++) {
            int h = lane*4 + q;
            double hv = (double)s[q] + (double)cc[q] + (double)b1[h];
            double gl = 0.5 * hv * (1.0 + erf(hv * 0.70710678118654752440));
            sd += gl * (double)W2[h];
        }
        #pragma unroll
        for (int o = 16; o; o >>= 1)
            sd += __shfl_xor_sync(0xffffffffu, sd, o);
        if (lane == 0) g_scores[b*N_ + r] = (float)sd;
        __syncwarp();
    }
}

// ---------------- kernel 5: exact top-K per batch on refined scores --------
__device__ __forceinline__ int block_exscan(int v, int* sw, int tid) {
    int lane = tid & 31, w = tid >> 5;
    int x = v;
    #pragma unroll
    for (int o = 1; o < 32; o <<= 1) {
        int y = __shfl_up_sync(0xffffffffu, x, o);
        if (lane >= o) x += y;
    }
    __syncthreads();
    if (lane == 31) sw[w] = x;
    __syncthreads();
    if (w == 0) {
        int s = sw[lane];
        #pragma unroll
        for (int o = 1; o < 32; o <<= 1) {
            int y = __shfl_up_sync(0xffffffffu, s, o);
            if (lane >= o) s += y;
        }
        sw[lane] = s;
    }
    __syncthreads();
    int base = (w == 0) ? 0 : sw[w-1];
    return base + x - v;
}

__global__ void __launch_bounds__(1024) select_topk() {
    __shared__ uint32_t keys[N_];
    __shared__ int hist[256];
    __shared__ int sw[32];
    __shared__ int sh_Krem;
    __shared__ uint32_t sh_prefix;

    const int b = blockIdx.x, tid = threadIdx.x;

    for (int i = tid; i < N_; i += 1024)
        keys[i] = fmap(g_scores[b*N_ + i]);
    __syncthreads();

    SelResult sel = radix_select_smem(keys, tid, hist, &sh_Krem, &sh_prefix);
    const uint32_t T = sel.T;
    const int need_eq = sel.need_eq;

    const int base_i = tid * 8;
    int eqc = 0;
    #pragma unroll
    for (int j = 0; j < 8; j++) eqc += (keys[base_i + j] == T);
    int e = block_exscan(eqc, sw, tid);

    int keepc = 0;
    unsigned char kp[8];
    #pragma unroll
    for (int j = 0; j < 8; j++) {
        uint32_t v = keys[base_i + j];
        bool k = (v > T);
        if (v == T) { k = (e < need_eq); e++; }
        kp[j] = k; keepc += k;
    }
    int pos = block_exscan(keepc, sw, tid);
    #pragma unroll
    for (int j = 0; j < 8; j++) {
        if (kp[j]) { g_idx[b*KEEP_ + pos] = base_i + j; pos++; }
    }
}

// ---------------- kernel 6: gather pruned tokens + emit indices ------------
__global__ void __launch_bounds__(512)
gather_rows(const float* __restrict__ tokens, float* __restrict__ out,
            int write_idx) {
    int rid = blockIdx.x * 16 + (threadIdx.x >> 5);
    if (rid >= B_*KEEP_) return;
    int lane = threadIdx.x & 31;
    int b = rid / KEEP_;
    int idx = g_idx[rid];
    const float4* s = (const float4*)(tokens + ((long long)(b*N_ + idx)) * C_);
    float4* d = (float4*)(out + (long long)rid * C_);
    d[lane]      = s[lane];
    d[lane + 32] = s[lane + 32];
    if (write_idx && lane == 0)
        out[(long long)B_*KEEP_*C_ + rid] = (float)idx;
}

// ---------------- launch ----------------------------------------------------
extern "C" void kernel_launch(void* const* d_in, const int* in_sizes, int n_in,
                              void* d_out, int out_size) {
    const float* tokens = (const float*)d_in[0];
    const float* W1     = (const float*)d_in[1];
    const float* b1     = (const float*)d_in[2];
    const float* W2     = (const float*)d_in[3];
    // b2 shifts all scores equally -> selection-invariant; not in output.

    prep_w1<<<32, 256>>>(W1);

    gemm_scores<<<M_/128, 256>>>(tokens, b1, W2);

    band_setup<<<B_, 1024>>>();

    refine_band<<<dim3(19, B_), 256>>>(tokens, W1, b1, W2);

    select_topk<<<B_, 1024>>>();

    long long prunedN = (long long)B_ * KEEP_ * C_;
    int wi = ((long long)out_size >= prunedN + (long long)B_*KEEP_) ? 1 : 0;
    gather_rows<<<(B_*KEEP_ + 15)/16, 512>>>(tokens, (float*)d_out, wi);
}